// round 11
// baseline (speedup 1.0000x reference)
#include <cuda_runtime.h>
#include <cuda_fp16.h>
#include <math.h>
#include <stdint.h>

#define N_TOK 384
#define TDIM 768
#define VDIM 768
#define CDIM 1536
#define FF_DIM 2048
#define NH 4
#define NLAYERS 2

// ---------------- fp32 scratch ----------------
#define OFF_X   0LL
#define OFF_X2  589824LL
#define OFF_QKV 1179648LL
#define OFF_SC  2949120LL
#define OFF_Y   4128768LL
#define OFF_A   5505024LL
#define OFF_C   5505792LL
#define OFF_RC  5506560LL
#define OFF_RL  5506944LL
#define OFF_CL  5507328LL
#define BUF_TOTAL 5507712LL
__device__ float g_buf[BUF_TOTAL];

// ---------------- fp16 activation shadows ----------------
#define HA_QKV  0LL
#define HA_X    1769472LL
#define HA_O    2359296LL
#define HA_H    2949120LL
#define HBUF_TOTAL 3735552LL
__device__ __half g_hbuf[HBUF_TOTAL];

// ---------------- PDL ----------------
__device__ __forceinline__ void pdl_wait() {
    asm volatile("griddepcontrol.wait;" ::: "memory");
}
__device__ __forceinline__ void pdl_go() {
    asm volatile("griddepcontrol.launch_dependents;" ::: "memory");
}

// ---------------- helpers ----------------
__device__ __forceinline__ unsigned f2tf(float x) {
    unsigned u;
    asm("cvt.rna.tf32.f32 %0, %1;" : "=r"(u) : "f"(x));
    return u;
}
__device__ __forceinline__ void mma8(float* c, const unsigned* a, const unsigned* b) {
    asm volatile(
        "mma.sync.aligned.m16n8k8.row.col.f32.tf32.tf32.f32 "
        "{%0,%1,%2,%3},{%4,%5,%6,%7},{%8,%9},{%0,%1,%2,%3};"
        : "+f"(c[0]), "+f"(c[1]), "+f"(c[2]), "+f"(c[3])
        : "r"(a[0]), "r"(a[1]), "r"(a[2]), "r"(a[3]), "r"(b[0]), "r"(b[1]));
}
__device__ __forceinline__ void mma16h(float* c, const unsigned* a, const unsigned* b) {
    asm volatile(
        "mma.sync.aligned.m16n8k16.row.col.f32.f16.f16.f32 "
        "{%0,%1,%2,%3},{%4,%5,%6,%7},{%8,%9},{%0,%1,%2,%3};"
        : "+f"(c[0]), "+f"(c[1]), "+f"(c[2]), "+f"(c[3])
        : "r"(a[0]), "r"(a[1]), "r"(a[2]), "r"(a[3]), "r"(b[0]), "r"(b[1]));
}
__device__ __forceinline__ void ldsm_x4(unsigned* r, uint32_t addr) {
    asm volatile("ldmatrix.sync.aligned.m8n8.x4.shared.b16 {%0,%1,%2,%3}, [%4];"
        : "=r"(r[0]), "=r"(r[1]), "=r"(r[2]), "=r"(r[3]) : "r"(addr));
}
__device__ __forceinline__ void cpa16(unsigned dst, const void* src) {
    asm volatile("cp.async.cg.shared.global [%0], [%1], 16;" :: "r"(dst), "l"(src));
}
__device__ __forceinline__ void cpa_commit() { asm volatile("cp.async.commit_group;"); }
template <int N>
__device__ __forceinline__ void cpa_wait() {
    asm volatile("cp.async.wait_group %0;" :: "n"(N));
}
__device__ __forceinline__ unsigned h2u(__half2 h) {
    return *(unsigned*)&h;
}

// ---------------- small kernels ----------------
__global__ void copy_k(float* __restrict__ dst, __half* __restrict__ dsth,
                       const float* __restrict__ src, int n) {
    pdl_wait();
    int i = blockIdx.x * blockDim.x + threadIdx.x;
    if (i < n) { float v = src[i]; dst[i] = v; dsth[i] = __float2half(v); }
    pdl_go();
}
__global__ void concat_k(float* __restrict__ dst, __half* __restrict__ dsth,
                         const float* __restrict__ te, const float* __restrict__ vis) {
    pdl_wait();
    int i = blockIdx.x * blockDim.x + threadIdx.x;
    if (i < N_TOK * CDIM) {
        int r = i / CDIM, c = i % CDIM;
        float v = (c < TDIM) ? te[r * TDIM + c] : vis[r * VDIM + (c - TDIM)];
        dst[i] = v; dsth[i] = __float2half(v);
    }
    pdl_go();
}

// ============ h16_nt: fp16 A, fp16 W (used for attention scores) ===========
#define HPAD 72
#define A16_BYTES (64 * HPAD * 2)        // 9216
#define B16_BYTES (128 * HPAD * 2)       // 18432
#define STG16 (A16_BYTES + B16_BYTES)    // 27648
#define H_SMEM (3 * STG16)               // 82944

__global__ void __launch_bounds__(256) h16_nt(
    const __half* __restrict__ A, int lda, long long aZ,
    const __half* __restrict__ W, int ldw, long long wZ,
    const float* __restrict__ Bias,
    float* __restrict__ C32, __half* __restrict__ C16,
    int ldc, long long cZ,
    int K, float alpha, int relu)
{
    extern __shared__ __half hsm[];
    uint32_t base = (uint32_t)__cvta_generic_to_shared(hsm);

    pdl_wait();
    A += blockIdx.z * aZ; W += blockIdx.z * wZ;

    int tid = threadIdx.x;
    int warp = tid >> 5, lane = tid & 31;
    int g = lane >> 2, tg = lane & 3;
    int wm = (warp >> 2) * 32, wn = (warp & 3) * 32;
    int m0 = blockIdx.y * 64, n0 = blockIdx.x * 128;

    int S = K / 64;
    float acc[2][4][4] = {};

    int aRow = (lane & 7) + ((lane >> 3) & 1) * 8;
    int aK   = ((lane >> 4) & 1) * 8;
    int bRow = ((lane >> 4) & 1) * 8 + (lane & 7);
    int bK   = ((lane >> 3) & 1) * 8;

    auto loadStage = [&](int s) {
        uint32_t st = base + (uint32_t)(s % 3) * STG16;
        const __half* Ak = A + (long long)s * 64;
        const __half* Wk = W + (long long)s * 64;
#pragma unroll
        for (int j = 0; j < 2; j++) {
            int c = tid + j * 256;
            int r = c >> 3, kq = (c & 7) * 8;
            cpa16(st + (uint32_t)r * 144u + (uint32_t)kq * 2u,
                  Ak + (long long)(m0 + r) * lda + kq);
        }
        uint32_t bs = st + A16_BYTES;
#pragma unroll
        for (int j = 0; j < 4; j++) {
            int c = tid + j * 256;
            int r = c >> 3, kq = (c & 7) * 8;
            cpa16(bs + (uint32_t)r * 144u + (uint32_t)kq * 2u,
                  Wk + (long long)(n0 + r) * ldw + kq);
        }
        cpa_commit();
    };

    loadStage(0);
    loadStage(1);

    for (int s = 0; s < S; s++) {
        if (s == S - 1) cpa_wait<0>(); else cpa_wait<1>();
        __syncthreads();
        if (s + 2 < S) loadStage(s + 2);
        else cpa_commit();

        uint32_t aB = base + (uint32_t)(s % 3) * STG16;
        uint32_t bB = aB + A16_BYTES;

        unsigned afr[2][2][4], bfr[2][2][4];
        auto loadFrag = [&](int ks, int buf) {
            int kb = ks * 16;
#pragma unroll
            for (int mt = 0; mt < 2; mt++)
                ldsm_x4(afr[buf][mt],
                        aB + (uint32_t)(wm + mt * 16 + aRow) * 144u
                           + (uint32_t)(kb + aK) * 2u);
#pragma unroll
            for (int p = 0; p < 2; p++)
                ldsm_x4(bfr[buf][p],
                        bB + (uint32_t)(wn + p * 16 + bRow) * 144u
                           + (uint32_t)(kb + bK) * 2u);
        };

        loadFrag(0, 0);
#pragma unroll
        for (int ks = 0; ks < 4; ks++) {
            int buf = ks & 1;
            if (ks < 3) loadFrag(ks + 1, buf ^ 1);
#pragma unroll
            for (int mt = 0; mt < 2; mt++)
#pragma unroll
                for (int nt = 0; nt < 4; nt++)
                    mma16h(acc[mt][nt], afr[buf][mt], &bfr[buf][nt >> 1][(nt & 1) * 2]);
        }
        __syncthreads();
    }

    float* C32p = C32 ? C32 + blockIdx.z * cZ : (float*)0;
    __half* C16p = C16 ? C16 + blockIdx.z * cZ : (__half*)0;
#pragma unroll
    for (int mt = 0; mt < 2; mt++) {
#pragma unroll
        for (int nt = 0; nt < 4; nt++) {
            int col = n0 + wn + nt * 8 + 2 * tg;
            float b0 = 0.f, b1 = 0.f;
            if (Bias) { b0 = Bias[col]; b1 = Bias[col + 1]; }
            int row = m0 + wm + mt * 16 + g;
            float v00 = acc[mt][nt][0] * alpha + b0;
            float v01 = acc[mt][nt][1] * alpha + b1;
            float v10 = acc[mt][nt][2] * alpha + b0;
            float v11 = acc[mt][nt][3] * alpha + b1;
            if (relu) {
                v00 = fmaxf(v00, 0.f); v01 = fmaxf(v01, 0.f);
                v10 = fmaxf(v10, 0.f); v11 = fmaxf(v11, 0.f);
            }
            if (C32p) {
                *(float2*)&C32p[(long long)row * ldc + col] = make_float2(v00, v01);
                *(float2*)&C32p[(long long)(row + 8) * ldc + col] = make_float2(v10, v11);
            }
            if (C16p) {
                *(__half2*)&C16p[(long long)row * ldc + col] = __floats2half2_rn(v00, v01);
                *(__half2*)&C16p[(long long)(row + 8) * ldc + col] = __floats2half2_rn(v10, v11);
            }
        }
    }
    pdl_go();
}

// ============ h32_nt: fp16 A, fp32 W read directly (weight GEMMs) ==========
// B staged fp32 (row pad 68 floats = 272 B); fragments via float2 LDS + cvt.
#define BPAD32 68
#define B32_BYTES (128 * BPAD32 * 4)      // 34816
#define STG32 (A16_BYTES + B32_BYTES)     // 44032
#define W32_SMEM (3 * STG32)              // 132096

__global__ void __launch_bounds__(256) h32_nt(
    const __half* __restrict__ A, int lda,
    const float* __restrict__ W, int ldw,
    const float* __restrict__ Bias,
    float* __restrict__ C32, __half* __restrict__ C16,
    int ldc,
    int K, int relu)
{
    extern __shared__ char sm32[];
    uint32_t base = (uint32_t)__cvta_generic_to_shared(sm32);

    pdl_wait();

    int tid = threadIdx.x;
    int warp = tid >> 5, lane = tid & 31;
    int g = lane >> 2, tg = lane & 3;
    int wm = (warp >> 2) * 32, wn = (warp & 3) * 32;
    int m0 = blockIdx.y * 64, n0 = blockIdx.x * 128;

    int S = K / 64;
    float acc[2][4][4] = {};

    int aRow = (lane & 7) + ((lane >> 3) & 1) * 8;
    int aK   = ((lane >> 4) & 1) * 8;

    auto loadStage = [&](int s) {
        uint32_t st = base + (uint32_t)(s % 3) * STG32;
        const __half* Ak = A + (long long)s * 64;
        const float*  Wk = W + (long long)s * 64;
#pragma unroll
        for (int j = 0; j < 2; j++) {
            int c = tid + j * 256;
            int r = c >> 3, kq = (c & 7) * 8;
            cpa16(st + (uint32_t)r * 144u + (uint32_t)kq * 2u,
                  Ak + (long long)(m0 + r) * lda + kq);
        }
        uint32_t bs = st + A16_BYTES;
#pragma unroll
        for (int j = 0; j < 8; j++) {
            int c = tid + j * 256;               // 0..2047
            int r = c >> 4, kq = (c & 15) * 4;   // row, float index
            cpa16(bs + (uint32_t)r * 272u + (uint32_t)kq * 4u,
                  Wk + (long long)(n0 + r) * ldw + kq);
        }
        cpa_commit();
    };

    loadStage(0);
    loadStage(1);

    for (int s = 0; s < S; s++) {
        if (s == S - 1) cpa_wait<0>(); else cpa_wait<1>();
        __syncthreads();
        if (s + 2 < S) loadStage(s + 2);
        else cpa_commit();

        uint32_t aB = base + (uint32_t)(s % 3) * STG32;
        const float* Bf = (const float*)(sm32 + (size_t)(s % 3) * STG32 + A16_BYTES);

        unsigned afr[2][2][4], bfr[2][4][2];
        auto loadFrag = [&](int ks, int buf) {
            int kb = ks * 16;
#pragma unroll
            for (int mt = 0; mt < 2; mt++)
                ldsm_x4(afr[buf][mt],
                        aB + (uint32_t)(wm + mt * 16 + aRow) * 144u
                           + (uint32_t)(kb + aK) * 2u);
#pragma unroll
            for (int nt = 0; nt < 4; nt++) {
                const float* p = &Bf[(wn + nt * 8 + g) * BPAD32 + kb + 2 * tg];
                float2 f0 = *(const float2*)(p);
                float2 f1 = *(const float2*)(p + 8);
                bfr[buf][nt][0] = h2u(__floats2half2_rn(f0.x, f0.y));
                bfr[buf][nt][1] = h2u(__floats2half2_rn(f1.x, f1.y));
            }
        };

        loadFrag(0, 0);
#pragma unroll
        for (int ks = 0; ks < 4; ks++) {
            int buf = ks & 1;
            if (ks < 3) loadFrag(ks + 1, buf ^ 1);
#pragma unroll
            for (int mt = 0; mt < 2; mt++)
#pragma unroll
                for (int nt = 0; nt < 4; nt++)
                    mma16h(acc[mt][nt], afr[buf][mt], bfr[buf][nt]);
        }
        __syncthreads();
    }

#pragma unroll
    for (int mt = 0; mt < 2; mt++) {
#pragma unroll
        for (int nt = 0; nt < 4; nt++) {
            int col = n0 + wn + nt * 8 + 2 * tg;
            float b0 = 0.f, b1 = 0.f;
            if (Bias) { b0 = Bias[col]; b1 = Bias[col + 1]; }
            int row = m0 + wm + mt * 16 + g;
            float v00 = acc[mt][nt][0] + b0;
            float v01 = acc[mt][nt][1] + b1;
            float v10 = acc[mt][nt][2] + b0;
            float v11 = acc[mt][nt][3] + b1;
            if (relu) {
                v00 = fmaxf(v00, 0.f); v01 = fmaxf(v01, 0.f);
                v10 = fmaxf(v10, 0.f); v11 = fmaxf(v11, 0.f);
            }
            if (C32) {
                *(float2*)&C32[(long long)row * ldc + col] = make_float2(v00, v01);
                *(float2*)&C32[(long long)(row + 8) * ldc + col] = make_float2(v10, v11);
            }
            if (C16) {
                *(__half2*)&C16[(long long)row * ldc + col] = __floats2half2_rn(v00, v01);
                *(__half2*)&C16[(long long)(row + 8) * ldc + col] = __floats2half2_rn(v10, v11);
            }
        }
    }
    pdl_go();
}

// ============ NN GEMM (attn @ V): fp32 in, fp16 out. 64x64 tile. ============
#define SPAD 20
__global__ void __launch_bounds__(128) tf32_nn(
    const float* __restrict__ A, int lda, long long aZ,
    const float* __restrict__ B, int ldb, long long bZ,
    __half* __restrict__ C16, int ldc, long long cZ,
    int K)
{
    pdl_wait();
    A += blockIdx.z * aZ; B += blockIdx.z * bZ; C16 += blockIdx.z * cZ;
    __shared__ unsigned As[2][64 * SPAD];
    __shared__ unsigned Bs[2][64 * SPAD];
    int tid = threadIdx.x;
    int warp = tid >> 5, lane = tid & 31;
    int g = lane >> 2, tg = lane & 3;
    int wm = (warp >> 1) * 32, wn = (warp & 1) * 32;
    int m0 = blockIdx.y * 64, n0 = blockIdx.x * 64;

    int lrow = tid >> 1;
    int lcol = (tid & 1) * 8;
    const float* Ap = A + (long long)(m0 + lrow) * lda + lcol;
    int sidx = lrow * SPAD + lcol;

    int f0 = tid * 2;
    int bk0 = f0 >> 4, bc0 = (f0 & 15) * 4;
    int bk1 = (f0 + 1) >> 4, bc1 = ((f0 + 1) & 15) * 4;
    const float* Bp0 = B + (long long)bk0 * ldb + n0 + bc0;
    const float* Bp1 = B + (long long)bk1 * ldb + n0 + bc1;

    float acc[2][4][4] = {};
    int ntile = K / 16;
    {
        float4 a0 = *(const float4*)(Ap);
        float4 a1 = *(const float4*)(Ap + 4);
        float4 v0 = *(const float4*)(Bp0);
        float4 v1 = *(const float4*)(Bp1);
        *(uint4*)&As[0][sidx]     = make_uint4(f2tf(a0.x), f2tf(a0.y), f2tf(a0.z), f2tf(a0.w));
        *(uint4*)&As[0][sidx + 4] = make_uint4(f2tf(a1.x), f2tf(a1.y), f2tf(a1.z), f2tf(a1.w));
        Bs[0][(bc0 + 0) * SPAD + bk0] = f2tf(v0.x);
        Bs[0][(bc0 + 1) * SPAD + bk0] = f2tf(v0.y);
        Bs[0][(bc0 + 2) * SPAD + bk0] = f2tf(v0.z);
        Bs[0][(bc0 + 3) * SPAD + bk0] = f2tf(v0.w);
        Bs[0][(bc1 + 0) * SPAD + bk1] = f2tf(v1.x);
        Bs[0][(bc1 + 1) * SPAD + bk1] = f2tf(v1.y);
        Bs[0][(bc1 + 2) * SPAD + bk1] = f2tf(v1.z);
        Bs[0][(bc1 + 3) * SPAD + bk1] = f2tf(v1.w);
    }
    __syncthreads();
    int p = 0;
    for (int it = 0; it < ntile; it++) {
        float4 na0, na1, nv0, nv1;
        if (it + 1 < ntile) {
            int ko = (it + 1) * 16;
            na0 = *(const float4*)(Ap + ko);
            na1 = *(const float4*)(Ap + ko + 4);
            nv0 = *(const float4*)(Bp0 + (long long)ko * ldb);
            nv1 = *(const float4*)(Bp1 + (long long)ko * ldb);
        }
#pragma unroll
        for (int ks = 0; ks < 2; ks++) {
            int kb = ks * 8;
            unsigned a[2][4], b[4][2];
#pragma unroll
            for (int mt = 0; mt < 2; mt++) {
                const unsigned* base2 = &As[p][(wm + mt * 16 + g) * SPAD + kb + tg];
                a[mt][0] = base2[0];
                a[mt][1] = base2[8 * SPAD];
                a[mt][2] = base2[4];
                a[mt][3] = base2[8 * SPAD + 4];
            }
#pragma unroll
            for (int nt = 0; nt < 4; nt++) {
                const unsigned* base2 = &Bs[p][(wn + nt * 8 + g) * SPAD + kb + tg];
                b[nt][0] = base2[0];
                b[nt][1] = base2[4];
            }
#pragma unroll
            for (int mt = 0; mt < 2; mt++)
#pragma unroll
                for (int nt = 0; nt < 4; nt++)
                    mma8(acc[mt][nt], a[mt], b[nt]);
        }
        if (it + 1 < ntile) {
            int q = p ^ 1;
            *(uint4*)&As[q][sidx]     = make_uint4(f2tf(na0.x), f2tf(na0.y), f2tf(na0.z), f2tf(na0.w));
            *(uint4*)&As[q][sidx + 4] = make_uint4(f2tf(na1.x), f2tf(na1.y), f2tf(na1.z), f2tf(na1.w));
            Bs[q][(bc0 + 0) * SPAD + bk0] = f2tf(nv0.x);
            Bs[q][(bc0 + 1) * SPAD + bk0] = f2tf(nv0.y);
            Bs[q][(bc0 + 2) * SPAD + bk0] = f2tf(nv0.z);
            Bs[q][(bc0 + 3) * SPAD + bk0] = f2tf(nv0.w);
            Bs[q][(bc1 + 0) * SPAD + bk1] = f2tf(nv1.x);
            Bs[q][(bc1 + 1) * SPAD + bk1] = f2tf(nv1.y);
            Bs[q][(bc1 + 2) * SPAD + bk1] = f2tf(nv1.z);
            Bs[q][(bc1 + 3) * SPAD + bk1] = f2tf(nv1.w);
        }
        __syncthreads();
        p ^= 1;
    }

#pragma unroll
    for (int mt = 0; mt < 2; mt++) {
#pragma unroll
        for (int nt = 0; nt < 4; nt++) {
            int col = n0 + wn + nt * 8 + 2 * tg;
            int row = m0 + wm + mt * 16 + g;
            *(__half2*)&C16[(long long)row * ldc + col] =
                __floats2half2_rn(acc[mt][nt][0], acc[mt][nt][1]);
            *(__half2*)&C16[(long long)(row + 8) * ldc + col] =
                __floats2half2_rn(acc[mt][nt][2], acc[mt][nt][3]);
        }
    }
    pdl_go();
}

// ---------------- row softmax (fp32) ----------------
__global__ void softmax_rows(float* __restrict__ S, int n) {
    pdl_wait();
    float* row = S + (long long)blockIdx.x * n;
    __shared__ float red[128];
    int tid = threadIdx.x;
    float m = -1e30f;
    for (int j = tid; j < n; j += 128) m = fmaxf(m, row[j]);
    red[tid] = m; __syncthreads();
    for (int off = 64; off; off >>= 1) {
        if (tid < off) red[tid] = fmaxf(red[tid], red[tid + off]);
        __syncthreads();
    }
    m = red[0]; __syncthreads();
    float s = 0.f;
    for (int j = tid; j < n; j += 128) { float e = expf(row[j] - m); row[j] = e; s += e; }
    red[tid] = s; __syncthreads();
    for (int off = 64; off; off >>= 1) {
        if (tid < off) red[tid] += red[tid + off];
        __syncthreads();
    }
    float inv = 1.0f / red[0];
    for (int j = tid; j < n; j += 128) row[j] *= inv;
    pdl_go();
}

// ---------------- x = LN(x + delta); fp16 shadow ----------------
__global__ void ln_res_kernel(float* __restrict__ x, __half* __restrict__ xh,
                              const float* __restrict__ delta,
                              const float* __restrict__ s, const float* __restrict__ b, int d) {
    pdl_wait();
    float* xr = x + (long long)blockIdx.x * d;
    __half* xhr = xh + (long long)blockIdx.x * d;
    const float* dr = delta + (long long)blockIdx.x * d;
    __shared__ float red[256];
    int tid = threadIdx.x;
    float sum = 0.f;
    for (int j = tid; j < d; j += 256) { float v = xr[j] + dr[j]; xr[j] = v; sum += v; }
    red[tid] = sum; __syncthreads();
    for (int off = 128; off; off >>= 1) {
        if (tid < off) red[tid] += red[tid + off];
        __syncthreads();
    }
    float mean = red[0] / d; __syncthreads();
    float s2 = 0.f;
    for (int j = tid; j < d; j += 256) { float v = xr[j] - mean; s2 += v * v; }
    red[tid] = s2; __syncthreads();
    for (int off = 128; off; off >>= 1) {
        if (tid < off) red[tid] += red[tid + off];
        __syncthreads();
    }
    float inv = rsqrtf(red[0] / d + 1e-5f);
    __syncthreads();
    for (int j = tid; j < d; j += 256) {
        float v = (xr[j] - mean) * inv * s[j] + b[j];
        xr[j] = v;
        xhr[j] = __float2half(v);
    }
    pdl_go();
}

// ---------------- final linear ----------------
__global__ void lin_kernel(const float* __restrict__ x, const float* __restrict__ w,
                           const float* __restrict__ b, float* __restrict__ a,
                           float* __restrict__ c) {
    pdl_wait();
    int i = blockIdx.x;
    const float* xr = x + (long long)i * CDIM;
    __shared__ float red[4][256];
    int tid = threadIdx.x;
    float s0 = 0, s1 = 0, s2 = 0, s3 = 0;
    for (int k = tid; k < CDIM; k += 256) {
        float xv = xr[k];
        s0 += xv * w[k];
        s1 += xv * w[2 * CDIM + k];
        s2 += xv * w[CDIM + k];
        s3 += xv * w[2 * CDIM + CDIM + k];
    }
    red[0][tid] = s0; red[1][tid] = s1; red[2][tid] = s2; red[3][tid] = s3;
    __syncthreads();
    for (int off = 128; off; off >>= 1) {
        if (tid < off) {
            red[0][tid] += red[0][tid + off];
            red[1][tid] += red[1][tid + off];
            red[2][tid] += red[2][tid + off];
            red[3][tid] += red[3][tid + off];
        }
        __syncthreads();
    }
    if (tid == 0) {
        a[2 * i]     = red[0][0] + b[0];
        a[2 * i + 1] = red[1][0] + b[1];
        c[2 * i]     = red[2][0];
        c[2 * i + 1] = red[3][0];
    }
    pdl_go();
}

// ---------------- pairwise probs + loss partials ----------------
__global__ void pair_kernel(const float* __restrict__ a, const float* __restrict__ c,
                            const int* __restrict__ gt, float* __restrict__ probs,
                            float* __restrict__ rowcell, float* __restrict__ rowlink) {
    pdl_wait();
    int i = blockIdx.x, j = threadIdx.x;
    float l0 = a[2 * i] + c[2 * j];
    float l1 = a[2 * i + 1] + c[2 * j + 1];
    float m = fmaxf(l0, l1);
    float e0 = expf(l0 - m), e1 = expf(l1 - m);
    float inv = 1.0f / (e0 + e1);
    float p0 = e0 * inv, p1 = e1 * inv;
    long long idx = ((long long)i * N_TOK + j) * 2;
    probs[idx] = p0; probs[idx + 1] = p1;
    float mm = fmaxf(p0, p1);
    float lse = mm + logf(expf(p0 - mm) + expf(p1 - mm));
    float pg = gt[i * N_TOK + j] ? p1 : p0;
    float cell = lse - pg;

    __shared__ float red[512];
    red[j] = cell;
    if (j < 128) red[384 + j] = 0.f;
    __syncthreads();
    for (int off = 256; off; off >>= 1) {
        if (j < off) red[j] += red[j + off];
        __syncthreads();
    }
    if (j == 0) rowcell[i] = red[0];
    __syncthreads();
    red[j] = p1;
    if (j < 128) red[384 + j] = 0.f;
    __syncthreads();
    for (int off = 256; off; off >>= 1) {
        if (j < off) red[j] += red[j + off];
        __syncthreads();
    }
    if (j == 0) rowlink[i] = red[0];
    pdl_go();
}

__global__ void col_kernel(const float* __restrict__ probs, float* __restrict__ collink) {
    pdl_wait();
    int j = blockIdx.x; int tid = threadIdx.x;
    float s = 0.f;
    for (int i = tid; i < N_TOK; i += 128) s += probs[((long long)i * N_TOK + j) * 2 + 1];
    __shared__ float red[128];
    red[tid] = s; __syncthreads();
    for (int off = 64; off; off >>= 1) {
        if (tid < off) red[tid] += red[tid + off];
        __syncthreads();
    }
    if (tid == 0) collink[j] = red[0];
    pdl_go();
}

__global__ void final_kernel(const float* __restrict__ rowcell, const float* __restrict__ rowlink,
                             const float* __restrict__ collink, float* __restrict__ out,
                             int out_size) {
    pdl_wait();
    __shared__ float r1[512], r2[512];
    int tid = threadIdx.x;
    r1[tid] = (tid < N_TOK) ? rowcell[tid] : 0.f;
    r2[tid] = (tid < N_TOK - 1) ? fabsf(rowlink[tid] + collink[tid] - 1.0f) : 0.f;
    __syncthreads();
    for (int off = 256; off; off >>= 1) {
        if (tid < off) { r1[tid] += r1[tid + off]; r2[tid] += r2[tid + off]; }
        __syncthreads();
    }
    if (tid == 0 && out_size >= N_TOK * N_TOK * 2 + 2) {
        out[N_TOK * N_TOK * 2]     = r1[0] / (float)N_TOK;
        out[N_TOK * N_TOK * 2 + 1] = r2[0];
    }
}

// ---------------- host orchestration (PDL launches) ----------------
static cudaLaunchAttribute g_attr[1];
template <typename F, typename... Args>
static inline void pl(F f, dim3 gr, dim3 bl, size_t sm, Args... args) {
    cudaLaunchConfig_t c = {};
    c.gridDim = gr; c.blockDim = bl; c.dynamicSmemBytes = sm; c.stream = 0;
    g_attr[0].id = cudaLaunchAttributeProgrammaticStreamSerialization;
    g_attr[0].val.programmaticStreamSerializationAllowed = 1;
    c.attrs = g_attr; c.numAttrs = 1;
    cudaLaunchKernelEx(&c, f, args...);
}

struct EncW {
    const float *qkv_w, *qkv_b, *out_w, *out_b, *ln1_s, *ln1_b;
    const float *ff1_w, *ff1_b, *ff2_w, *ff2_b, *ln2_s, *ln2_b;
};

static void run_encoder(float* x, __half* xh, int d, const EncW& w,
                        float* qkv, __half* qkvh, float* sc, __half* oh,
                        float* y, __half* hh) {
    const int M = N_TOK;
    const int hd = d / NH;
    const float scale = 1.0f / sqrtf((float)hd);
    for (int l = 0; l < NLAYERS; l++) {
        // qkv = x @ Wq^T + Bq (fp32 weights read directly)
        pl(h32_nt, dim3(3 * d / 128, M / 64, 1), dim3(256), W32_SMEM,
           (const __half*)xh, d, w.qkv_w + (long long)l * 3 * d * d, d,
           w.qkv_b + (long long)l * 3 * d, qkv, qkvh, 3 * d, d, 0);
        // scores = Q @ K^T * scale (fp16 activations both sides)
        pl(h16_nt, dim3(M / 128, M / 64, NH), dim3(256), H_SMEM,
           (const __half*)qkvh, 3 * d, (long long)hd, (const __half*)(qkvh + d), 3 * d, (long long)hd,
           (const float*)0, sc, (__half*)0, M, (long long)M * M, hd, scale, 0);
        pl(softmax_rows, dim3(NH * M), dim3(128), 0, sc, M);
        pl(tf32_nn, dim3(hd / 64, M / 64, NH), dim3(128), 0,
           (const float*)sc, M, (long long)M * M, (const float*)(qkv + 2 * d), (long long)(3 * d), (long long)hd,
           oh, d, (long long)hd, M);
        pl(h32_nt, dim3(d / 128, M / 64, 1), dim3(256), W32_SMEM,
           (const __half*)oh, d, w.out_w + (long long)l * d * d, d,
           w.out_b + (long long)l * d, y, (__half*)0, d, d, 0);
        pl(ln_res_kernel, dim3(M), dim3(256), 0,
           x, xh, (const float*)y, w.ln1_s + (long long)l * d, w.ln1_b + (long long)l * d, d);
        pl(h32_nt, dim3(FF_DIM / 128, M / 64, 1), dim3(256), W32_SMEM,
           (const __half*)xh, d, w.ff1_w + (long long)l * FF_DIM * d, d,
           w.ff1_b + (long long)l * FF_DIM, (float*)0, hh, FF_DIM, d, 1);
        pl(h32_nt, dim3(d / 128, M / 64, 1), dim3(256), W32_SMEM,
           (const __half*)hh, FF_DIM, w.ff2_w + (long long)l * d * FF_DIM, FF_DIM,
           w.ff2_b + (long long)l * d, y, (__half*)0, d, FF_DIM, 0);
        pl(ln_res_kernel, dim3(M), dim3(256), 0,
           x, xh, (const float*)y, w.ln2_s + (long long)l * d, w.ln2_b + (long long)l * d, d);
    }
}

extern "C" void kernel_launch(void* const* d_in, const int* in_sizes, int n_in,
                              void* d_out, int out_size) {
    const float* text   = (const float*)d_in[0];
    const float* vision = (const float*)d_in[1];
    const int*   gt     = (const int*)d_in[2];
    const float* lin_w  = (const float*)d_in[27];
    const float* lin_b  = (const float*)d_in[28];

    static int inited = 0;
    if (!inited) {
        cudaFuncSetAttribute(h16_nt, cudaFuncAttributeMaxDynamicSharedMemorySize, H_SMEM);
        cudaFuncSetAttribute(h32_nt, cudaFuncAttributeMaxDynamicSharedMemorySize, W32_SMEM);
        inited = 1;
    }

    float* buf = nullptr;
    cudaGetSymbolAddress((void**)&buf, g_buf);
    __half* hb = nullptr;
    cudaGetSymbolAddress((void**)&hb, g_hbuf);

    float* x    = buf + OFF_X;
    float* x2   = buf + OFF_X2;
    float* qkv  = buf + OFF_QKV;
    float* sc   = buf + OFF_SC;
    float* y    = buf + OFF_Y;
    float* ga   = buf + OFF_A;
    float* gc   = buf + OFF_C;
    float* rcel = buf + OFF_RC;
    float* rlnk = buf + OFF_RL;
    float* clnk = buf + OFF_CL;

    __half* qkvh = hb + HA_QKV;
    __half* xh   = hb + HA_X;
    __half* oh   = hb + HA_O;
    __half* hh   = hb + HA_H;

    EncW tw = {
        (const float*)d_in[3],  (const float*)d_in[4],  (const float*)d_in[5],
        (const float*)d_in[6],  (const float*)d_in[7],  (const float*)d_in[8],
        (const float*)d_in[9],  (const float*)d_in[10], (const float*)d_in[11],
        (const float*)d_in[12], (const float*)d_in[13], (const float*)d_in[14]
    };
    EncW cw = {
        (const float*)d_in[15], (const float*)d_in[16], (const float*)d_in[17],
        (const float*)d_in[18], (const float*)d_in[19], (const float*)d_in[20],
        (const float*)d_in[21], (const float*)d_in[22], (const float*)d_in[23],
        (const float*)d_in[24], (const float*)d_in[25], (const float*)d_in[26]
    };

    pl(copy_k, dim3((N_TOK * TDIM + 255) / 256), dim3(256), 0, x, xh, text, N_TOK * TDIM);
    run_encoder(x, xh, TDIM, tw, qkv, qkvh, sc, oh, y, hh);

    pl(concat_k, dim3((N_TOK * CDIM + 255) / 256), dim3(256), 0, x2, xh, (const float*)x, vision);
    run_encoder(x2, xh, CDIM, cw, qkv, qkvh, sc, oh, y, hh);

    pl(lin_kernel, dim3(N_TOK), dim3(256), 0, (const float*)x2, lin_w, lin_b, ga, gc);

    float* out = (float*)d_out;
    pl(pair_kernel, dim3(N_TOK), dim3(N_TOK), 0,
       (const float*)ga, (const float*)gc, gt, out, rcel, rlnk);
    pl(col_kernel, dim3(N_TOK), dim3(128), 0, (const float*)out, clnk);
    pl(final_kernel, dim3(1), dim3(512), 0,
       (const float*)rcel, (const float*)rlnk, (const float*)clnk, out, out_size);
}

// round 12
// speedup vs baseline: 1.4060x; 1.4060x over previous
#include <cuda_runtime.h>
#include <cuda_fp16.h>
#include <math.h>
#include <stdint.h>

#define N_TOK 384
#define TDIM 768
#define VDIM 768
#define CDIM 1536
#define FF_DIM 2048
#define NH 4
#define NLAYERS 2

// ---------------- fp32 scratch ----------------
#define OFF_X   0LL
#define OFF_X2  589824LL
#define OFF_SC  2949120LL
#define OFF_Y   4128768LL
#define OFF_A   5505024LL
#define OFF_C   5505792LL
#define OFF_RC  5506560LL
#define OFF_RL  5506944LL
#define OFF_CL  5507328LL
#define BUF_TOTAL 5507712LL
__device__ float g_buf[BUF_TOTAL];

// ---------------- fp16 scratch (converted weights + activation shadows) ----
#define HW_TQKV 0LL
#define HW_TOUT 3538944LL
#define HW_TFF1 4718592LL
#define HW_TFF2 7864320LL
#define HW_CQKV 11010048LL
#define HW_COUT 25165824LL
#define HW_CFF1 29884416LL
#define HW_CFF2 36175872LL
#define HA_QKV  42467328LL
#define HA_X    44236800LL
#define HA_O    44826624LL
#define HA_H    45416448LL
#define HBUF_TOTAL 46202880LL
__device__ __half g_hbuf[HBUF_TOTAL];

// ---------------- PDL ----------------
__device__ __forceinline__ void pdl_wait() {
    asm volatile("griddepcontrol.wait;" ::: "memory");
}
__device__ __forceinline__ void pdl_go() {
    asm volatile("griddepcontrol.launch_dependents;" ::: "memory");
}

// ---------------- helpers ----------------
__device__ __forceinline__ void mma16h(float* c, const unsigned* a, const unsigned* b) {
    asm volatile(
        "mma.sync.aligned.m16n8k16.row.col.f32.f16.f16.f32 "
        "{%0,%1,%2,%3},{%4,%5,%6,%7},{%8,%9},{%0,%1,%2,%3};"
        : "+f"(c[0]), "+f"(c[1]), "+f"(c[2]), "+f"(c[3])
        : "r"(a[0]), "r"(a[1]), "r"(a[2]), "r"(a[3]), "r"(b[0]), "r"(b[1]));
}
__device__ __forceinline__ void ldsm_x4(unsigned* r, uint32_t addr) {
    asm volatile("ldmatrix.sync.aligned.m8n8.x4.shared.b16 {%0,%1,%2,%3}, [%4];"
        : "=r"(r[0]), "=r"(r[1]), "=r"(r[2]), "=r"(r[3]) : "r"(addr));
}
__device__ __forceinline__ void ldsm_x4_t(unsigned* r, uint32_t addr) {
    asm volatile("ldmatrix.sync.aligned.m8n8.x4.trans.shared.b16 {%0,%1,%2,%3}, [%4];"
        : "=r"(r[0]), "=r"(r[1]), "=r"(r[2]), "=r"(r[3]) : "r"(addr));
}
__device__ __forceinline__ void cpa16(unsigned dst, const void* src) {
    asm volatile("cp.async.cg.shared.global [%0], [%1], 16;" :: "r"(dst), "l"(src));
}
__device__ __forceinline__ void cpa_commit() { asm volatile("cp.async.commit_group;"); }
template <int N>
__device__ __forceinline__ void cpa_wait() {
    asm volatile("cp.async.wait_group %0;" :: "n"(N));
}

// ---------------- merged weight conversion ----------------
struct ConvArgs {
    const float* src[8];
    long long dstOff[8];
    int cum[9];
};
__global__ void conv_all(ConvArgs a, __half* __restrict__ hbase) {
    int i = blockIdx.x * blockDim.x + threadIdx.x;
    if (i < a.cum[8]) {
#pragma unroll
        for (int k = 0; k < 8; k++) {
            if (i < a.cum[k + 1]) {
                int local = i - a.cum[k];
                float4 v = ((const float4*)a.src[k])[local];
                __half2* d = (__half2*)(hbase + a.dstOff[k]) + local * 2;
                d[0] = __floats2half2_rn(v.x, v.y);
                d[1] = __floats2half2_rn(v.z, v.w);
                break;
            }
        }
    }
    pdl_go();
}

__global__ void copy_k(float* __restrict__ dst, __half* __restrict__ dsth,
                       const float* __restrict__ src, int n) {
    pdl_wait();
    int i = blockIdx.x * blockDim.x + threadIdx.x;
    if (i < n) { float v = src[i]; dst[i] = v; dsth[i] = __float2half(v); }
    pdl_go();
}
__global__ void concat_k(float* __restrict__ dst, __half* __restrict__ dsth,
                         const float* __restrict__ te, const float* __restrict__ vis) {
    pdl_wait();
    int i = blockIdx.x * blockDim.x + threadIdx.x;
    if (i < N_TOK * CDIM) {
        int r = i / CDIM, c = i % CDIM;
        float v = (c < TDIM) ? te[r * TDIM + c] : vis[r * VDIM + (c - TDIM)];
        dst[i] = v; dsth[i] = __float2half(v);
    }
    pdl_go();
}

// ============ fp16 NT GEMM: C = alpha*A(MxK,row)@W(NxK,row)^T + bias ========
#define HPAD 72
#define A16_BYTES (64 * HPAD * 2)
#define B16_BYTES (128 * HPAD * 2)
#define STG16 (A16_BYTES + B16_BYTES)
#define H_SMEM (3 * STG16)

__global__ void __launch_bounds__(256) h16_nt(
    const __half* __restrict__ A, int lda, long long aZ,
    const __half* __restrict__ W, int ldw, long long wZ,
    const float* __restrict__ Bias,
    float* __restrict__ C32, __half* __restrict__ C16,
    int ldc, long long cZ,
    int K, float alpha, int relu)
{
    extern __shared__ __half hsm[];
    uint32_t base = (uint32_t)__cvta_generic_to_shared(hsm);

    pdl_wait();
    A += blockIdx.z * aZ; W += blockIdx.z * wZ;

    int tid = threadIdx.x;
    int warp = tid >> 5, lane = tid & 31;
    int g = lane >> 2, tg = lane & 3;
    int wm = (warp >> 2) * 32, wn = (warp & 3) * 32;
    int m0 = blockIdx.y * 64, n0 = blockIdx.x * 128;

    int S = K / 64;
    float acc[2][4][4] = {};

    int aRow = (lane & 7) + ((lane >> 3) & 1) * 8;
    int aK   = ((lane >> 4) & 1) * 8;
    int bRow = ((lane >> 4) & 1) * 8 + (lane & 7);
    int bK   = ((lane >> 3) & 1) * 8;

    auto loadStage = [&](int s) {
        uint32_t st = base + (uint32_t)(s % 3) * STG16;
        const __half* Ak = A + (long long)s * 64;
        const __half* Wk = W + (long long)s * 64;
#pragma unroll
        for (int j = 0; j < 2; j++) {
            int c = tid + j * 256;
            int r = c >> 3, kq = (c & 7) * 8;
            cpa16(st + (uint32_t)r * 144u + (uint32_t)kq * 2u,
                  Ak + (long long)(m0 + r) * lda + kq);
        }
        uint32_t bs = st + A16_BYTES;
#pragma unroll
        for (int j = 0; j < 4; j++) {
            int c = tid + j * 256;
            int r = c >> 3, kq = (c & 7) * 8;
            cpa16(bs + (uint32_t)r * 144u + (uint32_t)kq * 2u,
                  Wk + (long long)(n0 + r) * ldw + kq);
        }
        cpa_commit();
    };

    loadStage(0);
    loadStage(1);

    for (int s = 0; s < S; s++) {
        if (s == S - 1) cpa_wait<0>(); else cpa_wait<1>();
        __syncthreads();
        if (s + 2 < S) loadStage(s + 2);
        else cpa_commit();

        uint32_t aB = base + (uint32_t)(s % 3) * STG16;
        uint32_t bB = aB + A16_BYTES;

        unsigned afr[2][2][4], bfr[2][2][4];
        auto loadFrag = [&](int ks, int buf) {
            int kb = ks * 16;
#pragma unroll
            for (int mt = 0; mt < 2; mt++)
                ldsm_x4(afr[buf][mt],
                        aB + (uint32_t)(wm + mt * 16 + aRow) * 144u
                           + (uint32_t)(kb + aK) * 2u);
#pragma unroll
            for (int p = 0; p < 2; p++)
                ldsm_x4(bfr[buf][p],
                        bB + (uint32_t)(wn + p * 16 + bRow) * 144u
                           + (uint32_t)(kb + bK) * 2u);
        };

        loadFrag(0, 0);
#pragma unroll
        for (int ks = 0; ks < 4; ks++) {
            int buf = ks & 1;
            if (ks < 3) loadFrag(ks + 1, buf ^ 1);
#pragma unroll
            for (int mt = 0; mt < 2; mt++)
#pragma unroll
                for (int nt = 0; nt < 4; nt++)
                    mma16h(acc[mt][nt], afr[buf][mt], &bfr[buf][nt >> 1][(nt & 1) * 2]);
        }
        __syncthreads();
    }

    float* C32p = C32 ? C32 + blockIdx.z * cZ : (float*)0;
    __half* C16p = C16 ? C16 + blockIdx.z * cZ : (__half*)0;
#pragma unroll
    for (int mt = 0; mt < 2; mt++) {
#pragma unroll
        for (int nt = 0; nt < 4; nt++) {
            int col = n0 + wn + nt * 8 + 2 * tg;
            float b0 = 0.f, b1 = 0.f;
            if (Bias) { b0 = Bias[col]; b1 = Bias[col + 1]; }
            int row = m0 + wm + mt * 16 + g;
            float v00 = acc[mt][nt][0] * alpha + b0;
            float v01 = acc[mt][nt][1] * alpha + b1;
            float v10 = acc[mt][nt][2] * alpha + b0;
            float v11 = acc[mt][nt][3] * alpha + b1;
            if (relu) {
                v00 = fmaxf(v00, 0.f); v01 = fmaxf(v01, 0.f);
                v10 = fmaxf(v10, 0.f); v11 = fmaxf(v11, 0.f);
            }
            if (C32p) {
                *(float2*)&C32p[(long long)row * ldc + col] = make_float2(v00, v01);
                *(float2*)&C32p[(long long)(row + 8) * ldc + col] = make_float2(v10, v11);
            }
            if (C16p) {
                *(__half2*)&C16p[(long long)row * ldc + col] = __floats2half2_rn(v00, v01);
                *(__half2*)&C16p[(long long)(row + 8) * ldc + col] = __floats2half2_rn(v10, v11);
            }
        }
    }
    pdl_go();
}

// ============ fused softmax + attn@V =======================================
// Per CTA: head z, 64 q-rows, 64 v-cols. Softmax raw scores (fp32) into smem
// fp16 P; V panel [k=384][n=64] fp16 via cp.async; k-loop of mma with
// ldmatrix (P) + ldmatrix.trans (V). Output O fp16.
#define PPITCH 392                      // halves per P row
#define BPITCH 72                       // halves per V row
#define P_BYTES (64 * PPITCH * 2)       // 50176
#define BV_BYTES (384 * BPITCH * 2)     // 55296
#define ATT_SMEM (P_BYTES + BV_BYTES)   // 105472

__global__ void __launch_bounds__(128) attn_pv(
    const float* __restrict__ SC,   // [NH][N][N] raw scores
    const __half* __restrict__ V,   // qkvh + 2*d
    __half* __restrict__ O,         // [N][d] fp16
    int d, int hd)
{
    extern __shared__ char smraw[];
    __half* P = (__half*)smraw;
    uint32_t Pb = (uint32_t)__cvta_generic_to_shared(P);
    uint32_t Bb = Pb + P_BYTES;

    pdl_wait();

    int tid = threadIdx.x;
    int warp = tid >> 5, lane = tid & 31;
    int g = lane >> 2, tg = lane & 3;
    int wm = (warp >> 1) * 32, wn = (warp & 1) * 32;
    int z = blockIdx.z;
    int m0 = blockIdx.y * 64;
    int nc0 = blockIdx.x * 64;
    const float* sc = SC + (long long)z * N_TOK * N_TOK;
    const __half* Vb = V + (long long)z * hd + nc0;

    // V panel loads: 384 rows x 128B = 3072 chunks, 24 per thread
#pragma unroll
    for (int j = 0; j < 24; j++) {
        int c = tid + j * 128;
        int k = c >> 3, q = (c & 7) * 8;
        cpa16(Bb + (uint32_t)k * 144u + (uint32_t)q * 2u,
              Vb + (long long)k * (3 * d) + q);
    }
    cpa_commit();

    // softmax: row r = tid>>1, half h = tid&1 covers 192 cols
    {
        int r = tid >> 1, h = tid & 1;
        const float* row = sc + (long long)(m0 + r) * N_TOK + h * 192;
        float mx = -1e30f;
        for (int c = 0; c < 192; c += 4) {
            float4 v = *(const float4*)(row + c);
            mx = fmaxf(mx, fmaxf(fmaxf(v.x, v.y), fmaxf(v.z, v.w)));
        }
        mx = fmaxf(mx, __shfl_xor_sync(0xffffffffu, mx, 1));
        __half* pr = P + r * PPITCH + h * 192;
        float sm = 0.f;
        for (int c = 0; c < 192; c += 4) {
            float4 v = *(const float4*)(row + c);
            float e0 = expf(v.x - mx), e1 = expf(v.y - mx);
            float e2 = expf(v.z - mx), e3 = expf(v.w - mx);
            sm += (e0 + e1) + (e2 + e3);
            *(__half2*)(pr + c)     = __floats2half2_rn(e0, e1);
            *(__half2*)(pr + c + 2) = __floats2half2_rn(e2, e3);
        }
        sm += __shfl_xor_sync(0xffffffffu, sm, 1);
        float inv = 1.0f / sm;
        __half2 hinv = __floats2half2_rn(inv, inv);
        for (int c = 0; c < 192; c += 2) {
            __half2* p2 = (__half2*)(pr + c);
            *p2 = __hmul2(*p2, hinv);
        }
    }
    cpa_wait<0>();
    __syncthreads();

    // mma loop: K = 384, k16 steps
    int aRow = (lane & 7) + ((lane >> 3) & 1) * 8;
    int aK   = ((lane >> 4) & 1) * 8;
    int tKr  = ((lane >> 3) & 1) * 8 + (lane & 7);   // k-row within trans tile
    int tNc  = ((lane >> 4) & 1) * 8;                // n offset within 16-pair

    float acc[2][4][4] = {};
    unsigned afr[2][2][4], bfr[2][2][4];

    auto loadFrag = [&](int ks, int buf) {
        int kb = ks * 16;
#pragma unroll
        for (int mt = 0; mt < 2; mt++)
            ldsm_x4(afr[buf][mt],
                    Pb + (uint32_t)(wm + mt * 16 + aRow) * 784u
                       + (uint32_t)(kb + aK) * 2u);
#pragma unroll
        for (int p = 0; p < 2; p++)
            ldsm_x4_t(bfr[buf][p],
                      Bb + (uint32_t)(kb + tKr) * 144u
                         + (uint32_t)(wn + p * 16 + tNc) * 2u);
    };

    loadFrag(0, 0);
#pragma unroll
    for (int ks = 0; ks < 24; ks++) {
        int buf = ks & 1;
        if (ks < 23) loadFrag(ks + 1, buf ^ 1);
#pragma unroll
        for (int mt = 0; mt < 2; mt++)
#pragma unroll
            for (int nt = 0; nt < 4; nt++)
                mma16h(acc[mt][nt], afr[buf][mt], &bfr[buf][nt >> 1][(nt & 1) * 2]);
    }

    // epilogue: O[row][z*hd + nc0 + col] fp16
#pragma unroll
    for (int mt = 0; mt < 2; mt++) {
#pragma unroll
        for (int nt = 0; nt < 4; nt++) {
            int row = m0 + wm + mt * 16 + g;
            int col = z * hd + nc0 + wn + nt * 8 + 2 * tg;
            *(__half2*)&O[(long long)row * d + col] =
                __floats2half2_rn(acc[mt][nt][0], acc[mt][nt][1]);
            *(__half2*)&O[(long long)(row + 8) * d + col] =
                __floats2half2_rn(acc[mt][nt][2], acc[mt][nt][3]);
        }
    }
    pdl_go();
}

// ---------------- x = LN(x + delta); fp16 shadow ----------------
__global__ void ln_res_kernel(float* __restrict__ x, __half* __restrict__ xh,
                              const float* __restrict__ delta,
                              const float* __restrict__ s, const float* __restrict__ b, int d) {
    pdl_wait();
    float* xr = x + (long long)blockIdx.x * d;
    __half* xhr = xh + (long long)blockIdx.x * d;
    const float* dr = delta + (long long)blockIdx.x * d;
    __shared__ float red[256];
    int tid = threadIdx.x;
    float sum = 0.f;
    for (int j = tid; j < d; j += 256) { float v = xr[j] + dr[j]; xr[j] = v; sum += v; }
    red[tid] = sum; __syncthreads();
    for (int off = 128; off; off >>= 1) {
        if (tid < off) red[tid] += red[tid + off];
        __syncthreads();
    }
    float mean = red[0] / d; __syncthreads();
    float s2 = 0.f;
    for (int j = tid; j < d; j += 256) { float v = xr[j] - mean; s2 += v * v; }
    red[tid] = s2; __syncthreads();
    for (int off = 128; off; off >>= 1) {
        if (tid < off) red[tid] += red[tid + off];
        __syncthreads();
    }
    float inv = rsqrtf(red[0] / d + 1e-5f);
    __syncthreads();
    for (int j = tid; j < d; j += 256) {
        float v = (xr[j] - mean) * inv * s[j] + b[j];
        xr[j] = v;
        xhr[j] = __float2half(v);
    }
    pdl_go();
}

// ---------------- final linear ----------------
__global__ void lin_kernel(const float* __restrict__ x, const float* __restrict__ w,
                           const float* __restrict__ b, float* __restrict__ a,
                           float* __restrict__ c) {
    pdl_wait();
    int i = blockIdx.x;
    const float* xr = x + (long long)i * CDIM;
    __shared__ float red[4][256];
    int tid = threadIdx.x;
    float s0 = 0, s1 = 0, s2 = 0, s3 = 0;
    for (int k = tid; k < CDIM; k += 256) {
        float xv = xr[k];
        s0 += xv * w[k];
        s1 += xv * w[2 * CDIM + k];
        s2 += xv * w[CDIM + k];
        s3 += xv * w[2 * CDIM + CDIM + k];
    }
    red[0][tid] = s0; red[1][tid] = s1; red[2][tid] = s2; red[3][tid] = s3;
    __syncthreads();
    for (int off = 128; off; off >>= 1) {
        if (tid < off) {
            red[0][tid] += red[0][tid + off];
            red[1][tid] += red[1][tid + off];
            red[2][tid] += red[2][tid + off];
            red[3][tid] += red[3][tid + off];
        }
        __syncthreads();
    }
    if (tid == 0) {
        a[2 * i]     = red[0][0] + b[0];
        a[2 * i + 1] = red[1][0] + b[1];
        c[2 * i]     = red[2][0];
        c[2 * i + 1] = red[3][0];
    }
    pdl_go();
}

// ---------------- pairwise probs + loss partials ----------------
__global__ void pair_kernel(const float* __restrict__ a, const float* __restrict__ c,
                            const int* __restrict__ gt, float* __restrict__ probs,
                            float* __restrict__ rowcell, float* __restrict__ rowlink) {
    pdl_wait();
    int i = blockIdx.x, j = threadIdx.x;
    float l0 = a[2 * i] + c[2 * j];
    float l1 = a[2 * i + 1] + c[2 * j + 1];
    float m = fmaxf(l0, l1);
    float e0 = expf(l0 - m), e1 = expf(l1 - m);
    float inv = 1.0f / (e0 + e1);
    float p0 = e0 * inv, p1 = e1 * inv;
    long long idx = ((long long)i * N_TOK + j) * 2;
    probs[idx] = p0; probs[idx + 1] = p1;
    float mm = fmaxf(p0, p1);
    float lse = mm + logf(expf(p0 - mm) + expf(p1 - mm));
    float pg = gt[i * N_TOK + j] ? p1 : p0;
    float cell = lse - pg;

    __shared__ float red[512];
    red[j] = cell;
    if (j < 128) red[384 + j] = 0.f;
    __syncthreads();
    for (int off = 256; off; off >>= 1) {
        if (j < off) red[j] += red[j + off];
        __syncthreads();
    }
    if (j == 0) rowcell[i] = red[0];
    __syncthreads();
    red[j] = p1;
    if (j < 128) red[384 + j] = 0.f;
    __syncthreads();
    for (int off = 256; off; off >>= 1) {
        if (j < off) red[j] += red[j + off];
        __syncthreads();
    }
    if (j == 0) rowlink[i] = red[0];
    pdl_go();
}

__global__ void col_kernel(const float* __restrict__ probs, float* __restrict__ collink) {
    pdl_wait();
    int j = blockIdx.x; int tid = threadIdx.x;
    float s = 0.f;
    for (int i = tid; i < N_TOK; i += 128) s += probs[((long long)i * N_TOK + j) * 2 + 1];
    __shared__ float red[128];
    red[tid] = s; __syncthreads();
    for (int off = 64; off; off >>= 1) {
        if (tid < off) red[tid] += red[tid + off];
        __syncthreads();
    }
    if (tid == 0) collink[j] = red[0];
    pdl_go();
}

__global__ void final_kernel(const float* __restrict__ rowcell, const float* __restrict__ rowlink,
                             const float* __restrict__ collink, float* __restrict__ out,
                             int out_size) {
    pdl_wait();
    __shared__ float r1[512], r2[512];
    int tid = threadIdx.x;
    r1[tid] = (tid < N_TOK) ? rowcell[tid] : 0.f;
    r2[tid] = (tid < N_TOK - 1) ? fabsf(rowlink[tid] + collink[tid] - 1.0f) : 0.f;
    __syncthreads();
    for (int off = 256; off; off >>= 1) {
        if (tid < off) { r1[tid] += r1[tid + off]; r2[tid] += r2[tid + off]; }
        __syncthreads();
    }
    if (tid == 0 && out_size >= N_TOK * N_TOK * 2 + 2) {
        out[N_TOK * N_TOK * 2]     = r1[0] / (float)N_TOK;
        out[N_TOK * N_TOK * 2 + 1] = r2[0];
    }
}

// ---------------- host orchestration (PDL launches) ----------------
static cudaLaunchAttribute g_attr[1];
template <typename F, typename... Args>
static inline void pl(F f, dim3 gr, dim3 bl, size_t sm, Args... args) {
    cudaLaunchConfig_t c = {};
    c.gridDim = gr; c.blockDim = bl; c.dynamicSmemBytes = sm; c.stream = 0;
    g_attr[0].id = cudaLaunchAttributeProgrammaticStreamSerialization;
    g_attr[0].val.programmaticStreamSerializationAllowed = 1;
    c.attrs = g_attr; c.numAttrs = 1;
    cudaLaunchKernelEx(&c, f, args...);
}

struct EncW {
    const __half *qkv_h, *out_h, *ff1_h, *ff2_h;
    const float *qkv_b, *out_b, *ln1_s, *ln1_b, *ff1_b, *ff2_b, *ln2_s, *ln2_b;
};

static void run_encoder(float* x, __half* xh, int d, const EncW& w,
                        __half* qkvh, float* sc, __half* oh,
                        float* y, __half* hh) {
    const int M = N_TOK;
    const int hd = d / NH;
    const float scale = 1.0f / sqrtf((float)hd);
    for (int l = 0; l < NLAYERS; l++) {
        // qkv: fp16 output only (V consumed as fp16 now)
        pl(h16_nt, dim3(3 * d / 128, M / 64, 1), dim3(256), H_SMEM,
           (const __half*)xh, d, 0LL, w.qkv_h + (long long)l * 3 * d * d, d, 0LL,
           w.qkv_b + (long long)l * 3 * d, (float*)0, qkvh, 3 * d, 0LL, d, 1.f, 0);
        // raw scores (scaled) fp32
        pl(h16_nt, dim3(M / 128, M / 64, NH), dim3(256), H_SMEM,
           (const __half*)qkvh, 3 * d, (long long)hd, (const __half*)(qkvh + d), 3 * d, (long long)hd,
           (const float*)0, sc, (__half*)0, M, (long long)M * M, hd, scale, 0);
        // fused softmax + attn@V
        pl(attn_pv, dim3(hd / 64, M / 64, NH), dim3(128), ATT_SMEM,
           (const float*)sc, (const __half*)(qkvh + 2 * d), oh, d, hd);
        // out proj
        pl(h16_nt, dim3(d / 128, M / 64, 1), dim3(256), H_SMEM,
           (const __half*)oh, d, 0LL, w.out_h + (long long)l * d * d, d, 0LL,
           w.out_b + (long long)l * d, y, (__half*)0, d, 0LL, d, 1.f, 0);
        pl(ln_res_kernel, dim3(M), dim3(256), 0,
           x, xh, (const float*)y, w.ln1_s + (long long)l * d, w.ln1_b + (long long)l * d, d);
        pl(h16_nt, dim3(FF_DIM / 128, M / 64, 1), dim3(256), H_SMEM,
           (const __half*)xh, d, 0LL, w.ff1_h + (long long)l * FF_DIM * d, d, 0LL,
           w.ff1_b + (long long)l * FF_DIM, (float*)0, hh, FF_DIM, 0LL, d, 1.f, 1);
        pl(h16_nt, dim3(d / 128, M / 64, 1), dim3(256), H_SMEM,
           (const __half*)hh, FF_DIM, 0LL, w.ff2_h + (long long)l * d * FF_DIM, FF_DIM, 0LL,
           w.ff2_b + (long long)l * d, y, (__half*)0, d, 0LL, FF_DIM, 1.f, 0);
        pl(ln_res_kernel, dim3(M), dim3(256), 0,
           x, xh, (const float*)y, w.ln2_s + (long long)l * d, w.ln2_b + (long long)l * d, d);
    }
}

extern "C" void kernel_launch(void* const* d_in, const int* in_sizes, int n_in,
                              void* d_out, int out_size) {
    const float* text   = (const float*)d_in[0];
    const float* vision = (const float*)d_in[1];
    const int*   gt     = (const int*)d_in[2];
    const float* lin_w  = (const float*)d_in[27];
    const float* lin_b  = (const float*)d_in[28];

    static int inited = 0;
    if (!inited) {
        cudaFuncSetAttribute(h16_nt, cudaFuncAttributeMaxDynamicSharedMemorySize, H_SMEM);
        cudaFuncSetAttribute(attn_pv, cudaFuncAttributeMaxDynamicSharedMemorySize, ATT_SMEM);
        inited = 1;
    }

    float* buf = nullptr;
    cudaGetSymbolAddress((void**)&buf, g_buf);
    __half* hb = nullptr;
    cudaGetSymbolAddress((void**)&hb, g_hbuf);

    float* x    = buf + OFF_X;
    float* x2   = buf + OFF_X2;
    float* sc   = buf + OFF_SC;
    float* y    = buf + OFF_Y;
    float* ga   = buf + OFF_A;
    float* gc   = buf + OFF_C;
    float* rcel = buf + OFF_RC;
    float* rlnk = buf + OFF_RL;
    float* clnk = buf + OFF_CL;

    __half* qkvh = hb + HA_QKV;
    __half* xh   = hb + HA_X;
    __half* oh   = hb + HA_O;
    __half* hh   = hb + HA_H;

    ConvArgs ca;
    const long long offs[8] = {HW_TQKV, HW_TOUT, HW_TFF1, HW_TFF2,
                               HW_CQKV, HW_COUT, HW_CFF1, HW_CFF2};
    const int srcs[8] = {3, 5, 9, 11, 15, 17, 21, 23};
    const long long ns[8] = {3538944LL, 1179648LL, 3145728LL, 3145728LL,
                             14155776LL, 4718592LL, 6291456LL, 6291456LL};
    ca.cum[0] = 0;
    for (int i = 0; i < 8; i++) {
        ca.src[i] = (const float*)d_in[srcs[i]];
        ca.dstOff[i] = offs[i];
        ca.cum[i + 1] = ca.cum[i] + (int)(ns[i] / 4);
    }
    pl(conv_all, dim3((ca.cum[8] + 255) / 256), dim3(256), 0, ca, hb);

    EncW tw = {
        hb + HW_TQKV, hb + HW_TOUT, hb + HW_TFF1, hb + HW_TFF2,
        (const float*)d_in[4], (const float*)d_in[6],
        (const float*)d_in[7], (const float*)d_in[8],
        (const float*)d_in[10], (const float*)d_in[12],
        (const float*)d_in[13], (const float*)d_in[14]
    };
    EncW cw = {
        hb + HW_CQKV, hb + HW_COUT, hb + HW_CFF1, hb + HW_CFF2,
        (const float*)d_in[16], (const float*)d_in[18],
        (const float*)d_in[19], (const float*)d_in[20],
        (const float*)d_in[22], (const float*)d_in[24],
        (const float*)d_in[25], (const float*)d_in[26]
    };

    pl(copy_k, dim3((N_TOK * TDIM + 255) / 256), dim3(256), 0, x, xh, text, N_TOK * TDIM);
    run_encoder(x, xh, TDIM, tw, qkvh, sc, oh, y, hh);

    pl(concat_k, dim3((N_TOK * CDIM + 255) / 256), dim3(256), 0, x2, xh, (const float*)x, vision);
    run_encoder(x2, xh, CDIM, cw, qkvh, sc, oh, y, hh);

    pl(lin_kernel, dim3(N_TOK), dim3(256), 0, (const float*)x2, lin_w, lin_b, ga, gc);

    float* out = (float*)d_out;
    pl(pair_kernel, dim3(N_TOK), dim3(N_TOK), 0,
       (const float*)ga, (const float*)gc, gt, out, rcel, rlnk);
    pl(col_kernel, dim3(N_TOK), dim3(128), 0, (const float*)out, clnk);
    pl(final_kernel, dim3(1), dim3(512), 0,
       (const float*)rcel, (const float*)rlnk, (const float*)clnk, out, out_size);
}

// round 13
// speedup vs baseline: 1.5971x; 1.1359x over previous
#include <cuda_runtime.h>
#include <cuda_fp16.h>
#include <math.h>
#include <stdint.h>

#define N_TOK 384
#define TDIM 768
#define VDIM 768
#define CDIM 1536
#define FF_DIM 2048
#define NH 4
#define NLAYERS 2

// ---------------- fp32 scratch ----------------
#define OFF_X   0LL
#define OFF_X2  589824LL
#define OFF_SC  2949120LL
#define OFF_Y   4128768LL
#define OFF_A   5505024LL
#define OFF_C   5505792LL
#define OFF_RC  5506560LL
#define OFF_RL  5506944LL
#define OFF_CL  5507328LL
#define BUF_TOTAL 5507712LL
__device__ float g_buf[BUF_TOTAL];

// ---------------- fp16 scratch (converted weights + activation shadows) ----
#define HW_TQKV 0LL
#define HW_TOUT 3538944LL
#define HW_TFF1 4718592LL
#define HW_TFF2 7864320LL
#define HW_CQKV 11010048LL
#define HW_COUT 25165824LL
#define HW_CFF1 29884416LL
#define HW_CFF2 36175872LL
#define HA_QKV  42467328LL
#define HA_X    44236800LL
#define HA_O    44826624LL
#define HA_H    45416448LL
#define HBUF_TOTAL 46202880LL
__device__ __half g_hbuf[HBUF_TOTAL];

// ---------------- PDL ----------------
__device__ __forceinline__ void pdl_wait() {
    asm volatile("griddepcontrol.wait;" ::: "memory");
}
__device__ __forceinline__ void pdl_go() {
    asm volatile("griddepcontrol.launch_dependents;" ::: "memory");
}

// ---------------- helpers ----------------
__device__ __forceinline__ void mma16h(float* c, const unsigned* a, const unsigned* b) {
    asm volatile(
        "mma.sync.aligned.m16n8k16.row.col.f32.f16.f16.f32 "
        "{%0,%1,%2,%3},{%4,%5,%6,%7},{%8,%9},{%0,%1,%2,%3};"
        : "+f"(c[0]), "+f"(c[1]), "+f"(c[2]), "+f"(c[3])
        : "r"(a[0]), "r"(a[1]), "r"(a[2]), "r"(a[3]), "r"(b[0]), "r"(b[1]));
}
__device__ __forceinline__ void ldsm_x4(unsigned* r, uint32_t addr) {
    asm volatile("ldmatrix.sync.aligned.m8n8.x4.shared.b16 {%0,%1,%2,%3}, [%4];"
        : "=r"(r[0]), "=r"(r[1]), "=r"(r[2]), "=r"(r[3]) : "r"(addr));
}
__device__ __forceinline__ void ldsm_x4_t(unsigned* r, uint32_t addr) {
    asm volatile("ldmatrix.sync.aligned.m8n8.x4.trans.shared.b16 {%0,%1,%2,%3}, [%4];"
        : "=r"(r[0]), "=r"(r[1]), "=r"(r[2]), "=r"(r[3]) : "r"(addr));
}
__device__ __forceinline__ void cpa16(unsigned dst, const void* src) {
    asm volatile("cp.async.cg.shared.global [%0], [%1], 16;" :: "r"(dst), "l"(src));
}
__device__ __forceinline__ void cpa_commit() { asm volatile("cp.async.commit_group;"); }
template <int N>
__device__ __forceinline__ void cpa_wait() {
    asm volatile("cp.async.wait_group %0;" :: "n"(N));
}

// ---------------- merged weight conversion ----------------
struct ConvArgs {
    const float* src[8];
    long long dstOff[8];
    int cum[9];
};
__global__ void conv_all(ConvArgs a, __half* __restrict__ hbase) {
    int i = blockIdx.x * blockDim.x + threadIdx.x;
    if (i < a.cum[8]) {
#pragma unroll
        for (int k = 0; k < 8; k++) {
            if (i < a.cum[k + 1]) {
                int local = i - a.cum[k];
                float4 v = ((const float4*)a.src[k])[local];
                __half2* d = (__half2*)(hbase + a.dstOff[k]) + local * 2;
                d[0] = __floats2half2_rn(v.x, v.y);
                d[1] = __floats2half2_rn(v.z, v.w);
                break;
            }
        }
    }
    pdl_go();
}

__global__ void copy_k(float* __restrict__ dst, __half* __restrict__ dsth,
                       const float* __restrict__ src, int n) {
    pdl_wait();
    int i = blockIdx.x * blockDim.x + threadIdx.x;
    if (i < n) { float v = src[i]; dst[i] = v; dsth[i] = __float2half(v); }
    pdl_go();
}
__global__ void concat_k(float* __restrict__ dst, __half* __restrict__ dsth,
                         const float* __restrict__ te, const float* __restrict__ vis) {
    pdl_wait();
    int i = blockIdx.x * blockDim.x + threadIdx.x;
    if (i < N_TOK * CDIM) {
        int r = i / CDIM, c = i % CDIM;
        float v = (c < TDIM) ? te[r * TDIM + c] : vis[r * VDIM + (c - TDIM)];
        dst[i] = v; dsth[i] = __float2half(v);
    }
    pdl_go();
}

// ============ fp16 NT GEMM: 64x64 tile, 128 threads (chip-filling) =========
// BK=64 stages, 3-stage cp.async ring, ldmatrix fragments double-buffered.
#define HPAD 72
#define T16_BYTES (64 * HPAD * 2)        // 9216 per operand
#define STG16 (2 * T16_BYTES)            // 18432
#define H_SMEM (3 * STG16)               // 55296

__global__ void __launch_bounds__(128) h16_nt(
    const __half* __restrict__ A, int lda, long long aZ,
    const __half* __restrict__ W, int ldw, long long wZ,
    const float* __restrict__ Bias,
    float* __restrict__ C32, __half* __restrict__ C16,
    int ldc, long long cZ,
    int K, float alpha, int relu)
{
    extern __shared__ __half hsm[];
    uint32_t base = (uint32_t)__cvta_generic_to_shared(hsm);

    pdl_wait();
    A += blockIdx.z * aZ; W += blockIdx.z * wZ;

    int tid = threadIdx.x;
    int warp = tid >> 5, lane = tid & 31;
    int g = lane >> 2, tg = lane & 3;
    int wm = (warp >> 1) * 32, wn = (warp & 1) * 32;
    int m0 = blockIdx.y * 64, n0 = blockIdx.x * 64;

    int S = K / 64;
    float acc[2][4][4] = {};

    int aRow = (lane & 7) + ((lane >> 3) & 1) * 8;
    int aK   = ((lane >> 4) & 1) * 8;
    int bRow = ((lane >> 4) & 1) * 8 + (lane & 7);
    int bK   = ((lane >> 3) & 1) * 8;

    auto loadStage = [&](int s) {
        uint32_t st = base + (uint32_t)(s % 3) * STG16;
        const __half* Ak = A + (long long)s * 64;
        const __half* Wk = W + (long long)s * 64;
#pragma unroll
        for (int j = 0; j < 4; j++) {
            int c = tid + j * 128;
            int r = c >> 3, kq = (c & 7) * 8;
            cpa16(st + (uint32_t)r * 144u + (uint32_t)kq * 2u,
                  Ak + (long long)(m0 + r) * lda + kq);
        }
        uint32_t bs = st + T16_BYTES;
#pragma unroll
        for (int j = 0; j < 4; j++) {
            int c = tid + j * 128;
            int r = c >> 3, kq = (c & 7) * 8;
            cpa16(bs + (uint32_t)r * 144u + (uint32_t)kq * 2u,
                  Wk + (long long)(n0 + r) * ldw + kq);
        }
        cpa_commit();
    };

    loadStage(0);
    loadStage(1);

    for (int s = 0; s < S; s++) {
        if (s == S - 1) cpa_wait<0>(); else cpa_wait<1>();
        __syncthreads();
        if (s + 2 < S) loadStage(s + 2);
        else cpa_commit();

        uint32_t aB = base + (uint32_t)(s % 3) * STG16;
        uint32_t bB = aB + T16_BYTES;

        unsigned afr[2][2][4], bfr[2][2][4];
        auto loadFrag = [&](int ks, int buf) {
            int kb = ks * 16;
#pragma unroll
            for (int mt = 0; mt < 2; mt++)
                ldsm_x4(afr[buf][mt],
                        aB + (uint32_t)(wm + mt * 16 + aRow) * 144u
                           + (uint32_t)(kb + aK) * 2u);
#pragma unroll
            for (int p = 0; p < 2; p++)
                ldsm_x4(bfr[buf][p],
                        bB + (uint32_t)(wn + p * 16 + bRow) * 144u
                           + (uint32_t)(kb + bK) * 2u);
        };

        loadFrag(0, 0);
#pragma unroll
        for (int ks = 0; ks < 4; ks++) {
            int buf = ks & 1;
            if (ks < 3) loadFrag(ks + 1, buf ^ 1);
#pragma unroll
            for (int mt = 0; mt < 2; mt++)
#pragma unroll
                for (int nt = 0; nt < 4; nt++)
                    mma16h(acc[mt][nt], afr[buf][mt], &bfr[buf][nt >> 1][(nt & 1) * 2]);
        }
        __syncthreads();
    }

    float* C32p = C32 ? C32 + blockIdx.z * cZ : (float*)0;
    __half* C16p = C16 ? C16 + blockIdx.z * cZ : (__half*)0;
#pragma unroll
    for (int mt = 0; mt < 2; mt++) {
#pragma unroll
        for (int nt = 0; nt < 4; nt++) {
            int col = n0 + wn + nt * 8 + 2 * tg;
            float b0 = 0.f, b1 = 0.f;
            if (Bias) { b0 = Bias[col]; b1 = Bias[col + 1]; }
            int row = m0 + wm + mt * 16 + g;
            float v00 = acc[mt][nt][0] * alpha + b0;
            float v01 = acc[mt][nt][1] * alpha + b1;
            float v10 = acc[mt][nt][2] * alpha + b0;
            float v11 = acc[mt][nt][3] * alpha + b1;
            if (relu) {
                v00 = fmaxf(v00, 0.f); v01 = fmaxf(v01, 0.f);
                v10 = fmaxf(v10, 0.f); v11 = fmaxf(v11, 0.f);
            }
            if (C32p) {
                *(float2*)&C32p[(long long)row * ldc + col] = make_float2(v00, v01);
                *(float2*)&C32p[(long long)(row + 8) * ldc + col] = make_float2(v10, v11);
            }
            if (C16p) {
                *(__half2*)&C16p[(long long)row * ldc + col] = __floats2half2_rn(v00, v01);
                *(__half2*)&C16p[(long long)(row + 8) * ldc + col] = __floats2half2_rn(v10, v11);
            }
        }
    }
    pdl_go();
}

// ============ fused softmax + attn@V (unchanged from R12 winner) ===========
#define PPITCH 392
#define BPITCH 72
#define P_BYTES (64 * PPITCH * 2)
#define BV_BYTES (384 * BPITCH * 2)
#define ATT_SMEM (P_BYTES + BV_BYTES)

__global__ void __launch_bounds__(128) attn_pv(
    const float* __restrict__ SC,
    const __half* __restrict__ V,
    __half* __restrict__ O,
    int d, int hd)
{
    extern __shared__ char smraw[];
    __half* P = (__half*)smraw;
    uint32_t Pb = (uint32_t)__cvta_generic_to_shared(P);
    uint32_t Bb = Pb + P_BYTES;

    pdl_wait();

    int tid = threadIdx.x;
    int warp = tid >> 5, lane = tid & 31;
    int g = lane >> 2, tg = lane & 3;
    int wm = (warp >> 1) * 32, wn = (warp & 1) * 32;
    int z = blockIdx.z;
    int m0 = blockIdx.y * 64;
    int nc0 = blockIdx.x * 64;
    const float* sc = SC + (long long)z * N_TOK * N_TOK;
    const __half* Vb = V + (long long)z * hd + nc0;

#pragma unroll
    for (int j = 0; j < 24; j++) {
        int c = tid + j * 128;
        int k = c >> 3, q = (c & 7) * 8;
        cpa16(Bb + (uint32_t)k * 144u + (uint32_t)q * 2u,
              Vb + (long long)k * (3 * d) + q);
    }
    cpa_commit();

    {
        int r = tid >> 1, h = tid & 1;
        const float* row = sc + (long long)(m0 + r) * N_TOK + h * 192;
        float mx = -1e30f;
        for (int c = 0; c < 192; c += 4) {
            float4 v = *(const float4*)(row + c);
            mx = fmaxf(mx, fmaxf(fmaxf(v.x, v.y), fmaxf(v.z, v.w)));
        }
        mx = fmaxf(mx, __shfl_xor_sync(0xffffffffu, mx, 1));
        __half* pr = P + r * PPITCH + h * 192;
        float sm = 0.f;
        for (int c = 0; c < 192; c += 4) {
            float4 v = *(const float4*)(row + c);
            float e0 = expf(v.x - mx), e1 = expf(v.y - mx);
            float e2 = expf(v.z - mx), e3 = expf(v.w - mx);
            sm += (e0 + e1) + (e2 + e3);
            *(__half2*)(pr + c)     = __floats2half2_rn(e0, e1);
            *(__half2*)(pr + c + 2) = __floats2half2_rn(e2, e3);
        }
        sm += __shfl_xor_sync(0xffffffffu, sm, 1);
        float inv = 1.0f / sm;
        __half2 hinv = __floats2half2_rn(inv, inv);
        for (int c = 0; c < 192; c += 2) {
            __half2* p2 = (__half2*)(pr + c);
            *p2 = __hmul2(*p2, hinv);
        }
    }
    cpa_wait<0>();
    __syncthreads();

    int aRow = (lane & 7) + ((lane >> 3) & 1) * 8;
    int aK   = ((lane >> 4) & 1) * 8;
    int tKr  = ((lane >> 3) & 1) * 8 + (lane & 7);
    int tNc  = ((lane >> 4) & 1) * 8;

    float acc[2][4][4] = {};
    unsigned afr[2][2][4], bfr[2][2][4];

    auto loadFrag = [&](int ks, int buf) {
        int kb = ks * 16;
#pragma unroll
        for (int mt = 0; mt < 2; mt++)
            ldsm_x4(afr[buf][mt],
                    Pb + (uint32_t)(wm + mt * 16 + aRow) * 784u
                       + (uint32_t)(kb + aK) * 2u);
#pragma unroll
        for (int p = 0; p < 2; p++)
            ldsm_x4_t(bfr[buf][p],
                      Bb + (uint32_t)(kb + tKr) * 144u
                         + (uint32_t)(wn + p * 16 + tNc) * 2u);
    };

    loadFrag(0, 0);
#pragma unroll
    for (int ks = 0; ks < 24; ks++) {
        int buf = ks & 1;
        if (ks < 23) loadFrag(ks + 1, buf ^ 1);
#pragma unroll
        for (int mt = 0; mt < 2; mt++)
#pragma unroll
            for (int nt = 0; nt < 4; nt++)
                mma16h(acc[mt][nt], afr[buf][mt], &bfr[buf][nt >> 1][(nt & 1) * 2]);
    }

#pragma unroll
    for (int mt = 0; mt < 2; mt++) {
#pragma unroll
        for (int nt = 0; nt < 4; nt++) {
            int row = m0 + wm + mt * 16 + g;
            int col = z * hd + nc0 + wn + nt * 8 + 2 * tg;
            *(__half2*)&O[(long long)row * d + col] =
                __floats2half2_rn(acc[mt][nt][0], acc[mt][nt][1]);
            *(__half2*)&O[(long long)(row + 8) * d + col] =
                __floats2half2_rn(acc[mt][nt][2], acc[mt][nt][3]);
        }
    }
    pdl_go();
}

// ---------------- x = LN(x + delta); fp16 shadow ----------------
__global__ void ln_res_kernel(float* __restrict__ x, __half* __restrict__ xh,
                              const float* __restrict__ delta,
                              const float* __restrict__ s, const float* __restrict__ b, int d) {
    pdl_wait();
    float* xr = x + (long long)blockIdx.x * d;
    __half* xhr = xh + (long long)blockIdx.x * d;
    const float* dr = delta + (long long)blockIdx.x * d;
    __shared__ float red[256];
    int tid = threadIdx.x;
    float sum = 0.f;
    for (int j = tid; j < d; j += 256) { float v = xr[j] + dr[j]; xr[j] = v; sum += v; }
    red[tid] = sum; __syncthreads();
    for (int off = 128; off; off >>= 1) {
        if (tid < off) red[tid] += red[tid + off];
        __syncthreads();
    }
    float mean = red[0] / d; __syncthreads();
    float s2 = 0.f;
    for (int j = tid; j < d; j += 256) { float v = xr[j] - mean; s2 += v * v; }
    red[tid] = s2; __syncthreads();
    for (int off = 128; off; off >>= 1) {
        if (tid < off) red[tid] += red[tid + off];
        __syncthreads();
    }
    float inv = rsqrtf(red[0] / d + 1e-5f);
    __syncthreads();
    for (int j = tid; j < d; j += 256) {
        float v = (xr[j] - mean) * inv * s[j] + b[j];
        xr[j] = v;
        xhr[j] = __float2half(v);
    }
    pdl_go();
}

// ---------------- final linear ----------------
__global__ void lin_kernel(const float* __restrict__ x, const float* __restrict__ w,
                           const float* __restrict__ b, float* __restrict__ a,
                           float* __restrict__ c) {
    pdl_wait();
    int i = blockIdx.x;
    const float* xr = x + (long long)i * CDIM;
    __shared__ float red[4][256];
    int tid = threadIdx.x;
    float s0 = 0, s1 = 0, s2 = 0, s3 = 0;
    for (int k = tid; k < CDIM; k += 256) {
        float xv = xr[k];
        s0 += xv * w[k];
        s1 += xv * w[2 * CDIM + k];
        s2 += xv * w[CDIM + k];
        s3 += xv * w[2 * CDIM + CDIM + k];
    }
    red[0][tid] = s0; red[1][tid] = s1; red[2][tid] = s2; red[3][tid] = s3;
    __syncthreads();
    for (int off = 128; off; off >>= 1) {
        if (tid < off) {
            red[0][tid] += red[0][tid + off];
            red[1][tid] += red[1][tid + off];
            red[2][tid] += red[2][tid + off];
            red[3][tid] += red[3][tid + off];
        }
        __syncthreads();
    }
    if (tid == 0) {
        a[2 * i]     = red[0][0] + b[0];
        a[2 * i + 1] = red[1][0] + b[1];
        c[2 * i]     = red[2][0];
        c[2 * i + 1] = red[3][0];
    }
    pdl_go();
}

// ---------------- pairwise probs + loss partials ----------------
__global__ void pair_kernel(const float* __restrict__ a, const float* __restrict__ c,
                            const int* __restrict__ gt, float* __restrict__ probs,
                            float* __restrict__ rowcell, float* __restrict__ rowlink) {
    pdl_wait();
    int i = blockIdx.x, j = threadIdx.x;
    float l0 = a[2 * i] + c[2 * j];
    float l1 = a[2 * i + 1] + c[2 * j + 1];
    float m = fmaxf(l0, l1);
    float e0 = expf(l0 - m), e1 = expf(l1 - m);
    float inv = 1.0f / (e0 + e1);
    float p0 = e0 * inv, p1 = e1 * inv;
    long long idx = ((long long)i * N_TOK + j) * 2;
    probs[idx] = p0; probs[idx + 1] = p1;
    float mm = fmaxf(p0, p1);
    float lse = mm + logf(expf(p0 - mm) + expf(p1 - mm));
    float pg = gt[i * N_TOK + j] ? p1 : p0;
    float cell = lse - pg;

    __shared__ float red[512];
    red[j] = cell;
    if (j < 128) red[384 + j] = 0.f;
    __syncthreads();
    for (int off = 256; off; off >>= 1) {
        if (j < off) red[j] += red[j + off];
        __syncthreads();
    }
    if (j == 0) rowcell[i] = red[0];
    __syncthreads();
    red[j] = p1;
    if (j < 128) red[384 + j] = 0.f;
    __syncthreads();
    for (int off = 256; off; off >>= 1) {
        if (j < off) red[j] += red[j + off];
        __syncthreads();
    }
    if (j == 0) rowlink[i] = red[0];
    pdl_go();
}

__global__ void col_kernel(const float* __restrict__ probs, float* __restrict__ collink) {
    pdl_wait();
    int j = blockIdx.x; int tid = threadIdx.x;
    float s = 0.f;
    for (int i = tid; i < N_TOK; i += 128) s += probs[((long long)i * N_TOK + j) * 2 + 1];
    __shared__ float red[128];
    red[tid] = s; __syncthreads();
    for (int off = 64; off; off >>= 1) {
        if (tid < off) red[tid] += red[tid + off];
        __syncthreads();
    }
    if (tid == 0) collink[j] = red[0];
    pdl_go();
}

__global__ void final_kernel(const float* __restrict__ rowcell, const float* __restrict__ rowlink,
                             const float* __restrict__ collink, float* __restrict__ out,
                             int out_size) {
    pdl_wait();
    __shared__ float r1[512], r2[512];
    int tid = threadIdx.x;
    r1[tid] = (tid < N_TOK) ? rowcell[tid] : 0.f;
    r2[tid] = (tid < N_TOK - 1) ? fabsf(rowlink[tid] + collink[tid] - 1.0f) : 0.f;
    __syncthreads();
    for (int off = 256; off; off >>= 1) {
        if (tid < off) { r1[tid] += r1[tid + off]; r2[tid] += r2[tid + off]; }
        __syncthreads();
    }
    if (tid == 0 && out_size >= N_TOK * N_TOK * 2 + 2) {
        out[N_TOK * N_TOK * 2]     = r1[0] / (float)N_TOK;
        out[N_TOK * N_TOK * 2 + 1] = r2[0];
    }
}

// ---------------- host orchestration (PDL launches) ----------------
static cudaLaunchAttribute g_attr[1];
template <typename F, typename... Args>
static inline void pl(F f, dim3 gr, dim3 bl, size_t sm, Args... args) {
    cudaLaunchConfig_t c = {};
    c.gridDim = gr; c.blockDim = bl; c.dynamicSmemBytes = sm; c.stream = 0;
    g_attr[0].id = cudaLaunchAttributeProgrammaticStreamSerialization;
    g_attr[0].val.programmaticStreamSerializationAllowed = 1;
    c.attrs = g_attr; c.numAttrs = 1;
    cudaLaunchKernelEx(&c, f, args...);
}

struct EncW {
    const __half *qkv_h, *out_h, *ff1_h, *ff2_h;
    const float *qkv_b, *out_b, *ln1_s, *ln1_b, *ff1_b, *ff2_b, *ln2_s, *ln2_b;
};

static void run_encoder(float* x, __half* xh, int d, const EncW& w,
                        __half* qkvh, float* sc, __half* oh,
                        float* y, __half* hh) {
    const int M = N_TOK;
    const int hd = d / NH;
    const float scale = 1.0f / sqrtf((float)hd);
    for (int l = 0; l < NLAYERS; l++) {
        pl(h16_nt, dim3(3 * d / 64, M / 64, 1), dim3(128), H_SMEM,
           (const __half*)xh, d, 0LL, w.qkv_h + (long long)l * 3 * d * d, d, 0LL,
           w.qkv_b + (long long)l * 3 * d, (float*)0, qkvh, 3 * d, 0LL, d, 1.f, 0);
        pl(h16_nt, dim3(M / 64, M / 64, NH), dim3(128), H_SMEM,
           (const __half*)qkvh, 3 * d, (long long)hd, (const __half*)(qkvh + d), 3 * d, (long long)hd,
           (const float*)0, sc, (__half*)0, M, (long long)M * M, hd, scale, 0);
        pl(attn_pv, dim3(hd / 64, M / 64, NH), dim3(128), ATT_SMEM,
           (const float*)sc, (const __half*)(qkvh + 2 * d), oh, d, hd);
        pl(h16_nt, dim3(d / 64, M / 64, 1), dim3(128), H_SMEM,
           (const __half*)oh, d, 0LL, w.out_h + (long long)l * d * d, d, 0LL,
           w.out_b + (long long)l * d, y, (__half*)0, d, 0LL, d, 1.f, 0);
        pl(ln_res_kernel, dim3(M), dim3(256), 0,
           x, xh, (const float*)y, w.ln1_s + (long long)l * d, w.ln1_b + (long long)l * d, d);
        pl(h16_nt, dim3(FF_DIM / 64, M / 64, 1), dim3(128), H_SMEM,
           (const __half*)xh, d, 0LL, w.ff1_h + (long long)l * FF_DIM * d, d, 0LL,
           w.ff1_b + (long long)l * FF_DIM, (float*)0, hh, FF_DIM, 0LL, d, 1.f, 1);
        pl(h16_nt, dim3(d / 64, M / 64, 1), dim3(128), H_SMEM,
           (const __half*)hh, FF_DIM, 0LL, w.ff2_h + (long long)l * d * FF_DIM, FF_DIM, 0LL,
           w.ff2_b + (long long)l * d, y, (__half*)0, d, 0LL, FF_DIM, 1.f, 0);
        pl(ln_res_kernel, dim3(M), dim3(256), 0,
           x, xh, (const float*)y, w.ln2_s + (long long)l * d, w.ln2_b + (long long)l * d, d);
    }
}

extern "C" void kernel_launch(void* const* d_in, const int* in_sizes, int n_in,
                              void* d_out, int out_size) {
    const float* text   = (const float*)d_in[0];
    const float* vision = (const float*)d_in[1];
    const int*   gt     = (const int*)d_in[2];
    const float* lin_w  = (const float*)d_in[27];
    const float* lin_b  = (const float*)d_in[28];

    static int inited = 0;
    if (!inited) {
        cudaFuncSetAttribute(h16_nt, cudaFuncAttributeMaxDynamicSharedMemorySize, H_SMEM);
        cudaFuncSetAttribute(attn_pv, cudaFuncAttributeMaxDynamicSharedMemorySize, ATT_SMEM);
        inited = 1;
    }

    float* buf = nullptr;
    cudaGetSymbolAddress((void**)&buf, g_buf);
    __half* hb = nullptr;
    cudaGetSymbolAddress((void**)&hb, g_hbuf);

    float* x    = buf + OFF_X;
    float* x2   = buf + OFF_X2;
    float* sc   = buf + OFF_SC;
    float* y    = buf + OFF_Y;
    float* ga   = buf + OFF_A;
    float* gc   = buf + OFF_C;
    float* rcel = buf + OFF_RC;
    float* rlnk = buf + OFF_RL;
    float* clnk = buf + OFF_CL;

    __half* qkvh = hb + HA_QKV;
    __half* xh   = hb + HA_X;
    __half* oh   = hb + HA_O;
    __half* hh   = hb + HA_H;

    ConvArgs ca;
    const long long offs[8] = {HW_TQKV, HW_TOUT, HW_TFF1, HW_TFF2,
                               HW_CQKV, HW_COUT, HW_CFF1, HW_CFF2};
    const int srcs[8] = {3, 5, 9, 11, 15, 17, 21, 23};
    const long long ns[8] = {3538944LL, 1179648LL, 3145728LL, 3145728LL,
                             14155776LL, 4718592LL, 6291456LL, 6291456LL};
    ca.cum[0] = 0;
    for (int i = 0; i < 8; i++) {
        ca.src[i] = (const float*)d_in[srcs[i]];
        ca.dstOff[i] = offs[i];
        ca.cum[i + 1] = ca.cum[i] + (int)(ns[i] / 4);
    }
    pl(conv_all, dim3((ca.cum[8] + 255) / 256), dim3(256), 0, ca, hb);

    EncW tw = {
        hb + HW_TQKV, hb + HW_TOUT, hb + HW_TFF1, hb + HW_TFF2,
        (const float*)d_in[4], (const float*)d_in[6],
        (const float*)d_in[7], (const float*)d_in[8],
        (const float*)d_in[10], (const float*)d_in[12],
        (const float*)d_in[13], (const float*)d_in[14]
    };
    EncW cw = {
        hb + HW_CQKV, hb + HW_COUT, hb + HW_CFF1, hb + HW_CFF2,
        (const float*)d_in[16], (const float*)d_in[18],
        (const float*)d_in[19], (const float*)d_in[20],
        (const float*)d_in[22], (const float*)d_in[24],
        (const float*)d_in[25], (const float*)d_in[26]
    };

    pl(copy_k, dim3((N_TOK * TDIM + 255) / 256), dim3(256), 0, x, xh, text, N_TOK * TDIM);
    run_encoder(x, xh, TDIM, tw, qkvh, sc, oh, y, hh);

    pl(concat_k, dim3((N_TOK * CDIM + 255) / 256), dim3(256), 0, x2, xh, (const float*)x, vision);
    run_encoder(x2, xh, CDIM, cw, qkvh, sc, oh, y, hh);

    pl(lin_kernel, dim3(N_TOK), dim3(256), 0, (const float*)x2, lin_w, lin_b, ga, gc);

    float* out = (float*)d_out;
    pl(pair_kernel, dim3(N_TOK), dim3(N_TOK), 0,
       (const float*)ga, (const float*)gc, gt, out, rcel, rlnk);
    pl(col_kernel, dim3(N_TOK), dim3(128), 0, (const float*)out, clnk);
    pl(final_kernel, dim3(1), dim3(512), 0,
       (const float*)rcel, (const float*)rlnk, (const float*)clnk, out, out_size);
}